// round 3
// baseline (speedup 1.0000x reference)
#include <cuda_runtime.h>
#include <math.h>

#define Bsz   2
#define Tseq  2048
#define Cdim  1024
#define Hn    16
#define HD    64
#define BHn   (Bsz*Hn)          // 32
#define MROWS (Bsz*Tseq)        // 4096
#define QKVN  (3*Cdim)          // 3072

// ---- scratch (static device globals; no allocation) ----
__device__ float g_qkv[(size_t)MROWS * QKVN];     // [B*T, 3C]
__device__ float g_Q[(size_t)BHn * Tseq * HD];    // [B,H,T,hd]
__device__ float g_K[(size_t)BHn * Tseq * HD];
__device__ float g_V[(size_t)BHn * Tseq * HD];
__device__ float g_att[(size_t)MROWS * Cdim];     // [B,T,C] pre-projection

// ======================================================================
// C[M,N] = A[M,K] * B[N,K]^T    (both K-major, fp32)
// 128x128 block tile, BK=8, 256 threads, 8x8 register microtile.
// MODE 0: A = x (param),   C = g_qkv (global)
// MODE 1: A = g_att,       C = out (param)
// No host-side symbol lookups needed.
// ======================================================================
template<int MODE>
__global__ void __launch_bounds__(256) gemm_nt(const float* __restrict__ Aext,
                                               const float* __restrict__ Bm,
                                               float* __restrict__ Cext,
                                               int M, int N, int K)
{
    const float* A  = (MODE == 0) ? Aext : (const float*)g_att;
    float*       Cm = (MODE == 0) ? (float*)g_qkv : Cext;

    const int BK = 8;
    __shared__ float As[BK][128];   // [k][m]
    __shared__ float Bs[BK][128];   // [k][n]

    const int tid = threadIdx.x;
    const int tx = tid & 15;            // 0..15 -> n group
    const int ty = tid >> 4;            // 0..15 -> m group
    const int rowBase = blockIdx.y * 128;
    const int colBase = blockIdx.x * 128;
    const int lr = tid >> 1;            // 0..127 load row
    const int lc = (tid & 1) << 2;      // 0 or 4   load col (k)

    const float* Aptr = A + (size_t)(rowBase + lr) * K + lc;
    const float* Bptr = Bm + (size_t)(colBase + lr) * K + lc;

    float acc[8][8];
    #pragma unroll
    for (int i = 0; i < 8; ++i)
        #pragma unroll
        for (int j = 0; j < 8; ++j) acc[i][j] = 0.f;

    for (int k0 = 0; k0 < K; k0 += BK) {
        float4 a = *reinterpret_cast<const float4*>(Aptr + k0);
        float4 b = *reinterpret_cast<const float4*>(Bptr + k0);
        As[lc + 0][lr] = a.x;  As[lc + 1][lr] = a.y;
        As[lc + 2][lr] = a.z;  As[lc + 3][lr] = a.w;
        Bs[lc + 0][lr] = b.x;  Bs[lc + 1][lr] = b.y;
        Bs[lc + 2][lr] = b.z;  Bs[lc + 3][lr] = b.w;
        __syncthreads();

        #pragma unroll
        for (int kk = 0; kk < BK; ++kk) {
            float ar[8], br[8];
            float4 a0 = *reinterpret_cast<const float4*>(&As[kk][ty << 3]);
            float4 a1 = *reinterpret_cast<const float4*>(&As[kk][(ty << 3) + 4]);
            float4 b0 = *reinterpret_cast<const float4*>(&Bs[kk][tx << 3]);
            float4 b1 = *reinterpret_cast<const float4*>(&Bs[kk][(tx << 3) + 4]);
            ar[0]=a0.x; ar[1]=a0.y; ar[2]=a0.z; ar[3]=a0.w;
            ar[4]=a1.x; ar[5]=a1.y; ar[6]=a1.z; ar[7]=a1.w;
            br[0]=b0.x; br[1]=b0.y; br[2]=b0.z; br[3]=b0.w;
            br[4]=b1.x; br[5]=b1.y; br[6]=b1.z; br[7]=b1.w;
            #pragma unroll
            for (int i = 0; i < 8; ++i)
                #pragma unroll
                for (int j = 0; j < 8; ++j)
                    acc[i][j] = fmaf(ar[i], br[j], acc[i][j]);
        }
        __syncthreads();
    }

    #pragma unroll
    for (int i = 0; i < 8; ++i) {
        float* crow = Cm + (size_t)(rowBase + (ty << 3) + i) * N + colBase + (tx << 3);
        *reinterpret_cast<float4*>(crow) =
            make_float4(acc[i][0], acc[i][1], acc[i][2], acc[i][3]);
        *reinterpret_cast<float4*>(crow + 4) =
            make_float4(acc[i][4], acc[i][5], acc[i][6], acc[i][7]);
    }
}

// ======================================================================
// RoPE + QKV split/transpose: g_qkv[B,T,3C] -> g_Q/g_K (rotated), g_V
// in [B,H,T,hd] layout. cos/sin computed in double on the fly.
// One thread per (b,t,h,j) with j in [0,32).
// ======================================================================
__global__ void rope_kernel()
{
    int idx = blockIdx.x * blockDim.x + threadIdx.x;
    int j = idx & 31;
    int h = (idx >> 5) & (Hn - 1);
    int t = (idx >> 9) & (Tseq - 1);
    int b = idx >> 20;

    size_t base = (size_t)(b * Tseq + t) * QKVN;
    int qo = h * HD + j;

    // inv_freq[j] = 10000^(-j/32);  phase = t * inv_freq[j]
    double invf = exp(-(double)j * (9.210340371976184 / 32.0)); // ln(10000)
    double ph = (double)t * invf;
    double sd, cd;
    sincos(ph, &sd, &cd);
    float c = (float)cd, s = (float)sd;

    size_t o = ((size_t)(b * Hn + h) * Tseq + t) * HD + j;

    float q0 = g_qkv[base + qo];
    float q1 = g_qkv[base + qo + 32];
    g_Q[o]      = q0 * c - q1 * s;
    g_Q[o + 32] = q1 * c + q0 * s;

    float k0 = g_qkv[base + Cdim + qo];
    float k1 = g_qkv[base + Cdim + qo + 32];
    g_K[o]      = k0 * c - k1 * s;
    g_K[o + 32] = k1 * c + k0 * s;

    g_V[o]      = g_qkv[base + 2 * Cdim + qo];
    g_V[o + 32] = g_qkv[base + 2 * Cdim + qo + 32];
}

// ======================================================================
// Flash attention, fp32, causal. 1 block = 64 query rows of one (b,h).
// 64 threads; each thread owns one query row (q + acc in registers).
// K/V 64x64 tiles in shared. Online softmax, per-tile rescale.
// smem = 2*16KB (K,V) + 16KB (scores) = 48KB exactly.
// ======================================================================
__global__ void __launch_bounds__(64) attn_kernel()
{
    const int qtile = blockIdx.x;    // 0..31
    const int bh    = blockIdx.y;    // 0..31 (b*H + h)
    const int tid   = threadIdx.x;   // 0..63

    const float* Qp = g_Q + (size_t)bh * Tseq * HD;
    const float* Kp = g_K + (size_t)bh * Tseq * HD;
    const float* Vp = g_V + (size_t)bh * Tseq * HD;

    const int qi = qtile * 64 + tid;

    float q[HD];
    {
        const float* qrow = Qp + (size_t)qi * HD;
        #pragma unroll
        for (int d = 0; d < HD; ++d) q[d] = qrow[d] * 0.125f;  // 1/sqrt(64)
    }

    float acc[HD];
    #pragma unroll
    for (int d = 0; d < HD; ++d) acc[d] = 0.f;
    float m = -1e30f, l = 0.f;

    __shared__ float ks[64][HD];
    __shared__ float vs[64][HD];
    __shared__ float sbuf[64][64];   // [j][thread] -- conflict-free

    for (int t0 = 0; t0 <= qtile; ++t0) {
        __syncthreads();
        // cooperative, coalesced tile load: thread tid owns column d = tid
        for (int r = 0; r < 64; ++r) {
            size_t g = (size_t)(t0 * 64 + r) * HD + tid;
            ks[r][tid] = Kp[g];
            vs[r][tid] = Vp[g];
        }
        __syncthreads();

        const int jmax = (t0 == qtile) ? tid : 63;

        float tmax = -1e30f;
        for (int j = 0; j <= jmax; ++j) {
            float s = 0.f;
            #pragma unroll
            for (int d = 0; d < HD; ++d) s = fmaf(q[d], ks[j][d], s);
            sbuf[j][tid] = s;
            tmax = fmaxf(tmax, s);
        }

        float mnew = fmaxf(m, tmax);
        float corr = __expf(m - mnew);
        l *= corr;
        #pragma unroll
        for (int d = 0; d < HD; ++d) acc[d] *= corr;

        for (int j = 0; j <= jmax; ++j) {
            float p = __expf(sbuf[j][tid] - mnew);
            l += p;
            #pragma unroll
            for (int d = 0; d < HD; ++d) acc[d] = fmaf(p, vs[j][d], acc[d]);
        }
        m = mnew;
    }

    const float inv = 1.f / l;
    const int b = bh >> 4;
    const int h = bh & 15;
    float* op = g_att + (size_t)(b * Tseq + qi) * Cdim + h * HD;
    #pragma unroll
    for (int d = 0; d < HD; ++d) op[d] = acc[d] * inv;
}

// ======================================================================
extern "C" void kernel_launch(void* const* d_in, const int* in_sizes, int n_in,
                              void* d_out, int out_size)
{
    const float* x      = (const float*)d_in[0];
    const float* w_attn = (const float*)d_in[1];
    const float* w_proj = (const float*)d_in[2];
    float* out = (float*)d_out;

    // 1) QKV = x @ w_attn^T : [4096,1024] x [3072,1024]^T -> g_qkv
    gemm_nt<0><<<dim3(QKVN / 128, MROWS / 128), 256>>>(x, w_attn, nullptr,
                                                       MROWS, QKVN, Cdim);

    // 2) RoPE + split to [B,H,T,hd]
    rope_kernel<<<(Bsz * Tseq * Hn * 32) / 256, 256>>>();

    // 3) causal flash attention -> g_att [B,T,C]
    attn_kernel<<<dim3(Tseq / 64, BHn), 64>>>();

    // 4) out = g_att @ w_proj^T : [4096,1024] x [1024,1024]^T
    gemm_nt<1><<<dim3(Cdim / 128, MROWS / 128), 256>>>(nullptr, w_proj, out,
                                                       MROWS, Cdim, Cdim);
}

// round 4
// speedup vs baseline: 1.1041x; 1.1041x over previous
#include <cuda_runtime.h>
#include <math.h>

#define Bsz   2
#define Tseq  2048
#define Cdim  1024
#define Hn    16
#define HD    64
#define BHn   (Bsz*Hn)          // 32
#define MROWS (Bsz*Tseq)        // 4096
#define QKVN  (3*Cdim)          // 3072

// ---- scratch (static device globals; no allocation) ----
__device__ float g_qkv[(size_t)MROWS * QKVN];     // [B*T, 3C]
__device__ float g_Q[(size_t)BHn * Tseq * HD];    // [B,H,T,hd]
__device__ float g_K[(size_t)BHn * Tseq * HD];
__device__ float g_V[(size_t)BHn * Tseq * HD];
__device__ float g_att[(size_t)MROWS * Cdim];     // [B,T,C] pre-projection
__device__ float g_cos[Tseq * 32];                // rope tables [t][j]
__device__ float g_sin[Tseq * 32];

// ======================================================================
// C[M,N] = A[M,K] * B[N,K]^T    (both K-major, fp32)
// 128x128 tile, BK=16, 256 threads, 8x8 microtile, reg-prefetch pipeline.
// MODE 0: A = x (param), C = g_qkv.   MODE 1: A = g_att, C = out (param).
// ======================================================================
template<int MODE>
__global__ void __launch_bounds__(256) gemm_nt(const float* __restrict__ Aext,
                                               const float* __restrict__ Bm,
                                               float* __restrict__ Cext,
                                               int M, int N, int K)
{
    const float* A  = (MODE == 0) ? Aext : (const float*)g_att;
    float*       Cm = (MODE == 0) ? (float*)g_qkv : Cext;

    const int BK = 16;
    __shared__ float As[BK][128];   // [k][m]
    __shared__ float Bs[BK][128];   // [k][n]

    const int tid = threadIdx.x;
    const int tx = tid & 15;            // n group
    const int ty = tid >> 4;            // m group
    const int rowBase = blockIdx.y * 128;
    const int colBase = blockIdx.x * 128;
    const int lr = tid >> 1;            // 0..127
    const int lc = (tid & 1) << 3;      // 0 or 8

    const float* Aptr = A + (size_t)(rowBase + lr) * K + lc;
    const float* Bptr = Bm + (size_t)(colBase + lr) * K + lc;

    float acc[8][8];
    #pragma unroll
    for (int i = 0; i < 8; ++i)
        #pragma unroll
        for (int j = 0; j < 8; ++j) acc[i][j] = 0.f;

    // prefetch first tile into registers
    float4 pa0 = *reinterpret_cast<const float4*>(Aptr);
    float4 pa1 = *reinterpret_cast<const float4*>(Aptr + 4);
    float4 pb0 = *reinterpret_cast<const float4*>(Bptr);
    float4 pb1 = *reinterpret_cast<const float4*>(Bptr + 4);

    for (int k0 = 0; k0 < K; k0 += BK) {
        As[lc+0][lr]=pa0.x; As[lc+1][lr]=pa0.y; As[lc+2][lr]=pa0.z; As[lc+3][lr]=pa0.w;
        As[lc+4][lr]=pa1.x; As[lc+5][lr]=pa1.y; As[lc+6][lr]=pa1.z; As[lc+7][lr]=pa1.w;
        Bs[lc+0][lr]=pb0.x; Bs[lc+1][lr]=pb0.y; Bs[lc+2][lr]=pb0.z; Bs[lc+3][lr]=pb0.w;
        Bs[lc+4][lr]=pb1.x; Bs[lc+5][lr]=pb1.y; Bs[lc+6][lr]=pb1.z; Bs[lc+7][lr]=pb1.w;
        __syncthreads();

        if (k0 + BK < K) {   // issue next-tile loads; they fly during compute
            pa0 = *reinterpret_cast<const float4*>(Aptr + k0 + BK);
            pa1 = *reinterpret_cast<const float4*>(Aptr + k0 + BK + 4);
            pb0 = *reinterpret_cast<const float4*>(Bptr + k0 + BK);
            pb1 = *reinterpret_cast<const float4*>(Bptr + k0 + BK + 4);
        }

        #pragma unroll
        for (int kk = 0; kk < BK; ++kk) {
            float4 a0 = *reinterpret_cast<const float4*>(&As[kk][ty << 3]);
            float4 a1 = *reinterpret_cast<const float4*>(&As[kk][(ty << 3) + 4]);
            float4 b0 = *reinterpret_cast<const float4*>(&Bs[kk][tx << 3]);
            float4 b1 = *reinterpret_cast<const float4*>(&Bs[kk][(tx << 3) + 4]);
            float ar[8] = {a0.x,a0.y,a0.z,a0.w,a1.x,a1.y,a1.z,a1.w};
            float br[8] = {b0.x,b0.y,b0.z,b0.w,b1.x,b1.y,b1.z,b1.w};
            #pragma unroll
            for (int i = 0; i < 8; ++i)
                #pragma unroll
                for (int j = 0; j < 8; ++j)
                    acc[i][j] = fmaf(ar[i], br[j], acc[i][j]);
        }
        __syncthreads();
    }

    #pragma unroll
    for (int i = 0; i < 8; ++i) {
        float* crow = Cm + (size_t)(rowBase + (ty << 3) + i) * N + colBase + (tx << 3);
        *reinterpret_cast<float4*>(crow) =
            make_float4(acc[i][0], acc[i][1], acc[i][2], acc[i][3]);
        *reinterpret_cast<float4*>(crow + 4) =
            make_float4(acc[i][4], acc[i][5], acc[i][6], acc[i][7]);
    }
}

// ======================================================================
// RoPE tables: computed once per launch in double (accuracy), tiny kernel.
// ======================================================================
__global__ void rope_table_kernel()
{
    int idx = blockIdx.x * blockDim.x + threadIdx.x;   // [0, Tseq*32)
    int j = idx & 31;
    int t = idx >> 5;
    double invf = exp(-(double)j * (9.210340371976184 / 32.0)); // ln(10000)
    double sd, cd;
    sincos((double)t * invf, &sd, &cd);
    g_cos[idx] = (float)cd;
    g_sin[idx] = (float)sd;
}

// ======================================================================
// RoPE + QKV split/transpose: g_qkv[B,T,3C] -> g_Q/g_K (rotated), g_V
// in [B,H,T,hd]. One thread per (b,t,h,j), j in [0,32).
// ======================================================================
__global__ void rope_kernel()
{
    int idx = blockIdx.x * blockDim.x + threadIdx.x;
    int j = idx & 31;
    int h = (idx >> 5) & (Hn - 1);
    int t = (idx >> 9) & (Tseq - 1);
    int b = idx >> 20;

    size_t base = (size_t)(b * Tseq + t) * QKVN;
    int qo = h * HD + j;

    float c = g_cos[(t << 5) + j];
    float s = g_sin[(t << 5) + j];

    size_t o = ((size_t)(b * Hn + h) * Tseq + t) * HD + j;

    float q0 = g_qkv[base + qo];
    float q1 = g_qkv[base + qo + 32];
    g_Q[o]      = q0 * c - q1 * s;
    g_Q[o + 32] = q1 * c + q0 * s;

    float k0 = g_qkv[base + Cdim + qo];
    float k1 = g_qkv[base + Cdim + qo + 32];
    g_K[o]      = k0 * c - k1 * s;
    g_K[o + 32] = k1 * c + k0 * s;

    g_V[o]      = g_qkv[base + 2 * Cdim + qo];
    g_V[o + 32] = g_qkv[base + 2 * Cdim + qo + 32];
}

// ======================================================================
// Flash attention, fp32, causal. 1 block = 64 query rows of one (b,h),
// 64 threads, thread owns a row. float4 everywhere; uniform loops with
// -1e30 masking on the diagonal tile. smem = 48KB exactly.
// ======================================================================
__global__ void __launch_bounds__(64) attn_kernel()
{
    const int qtile = blockIdx.x;    // 0..31
    const int bh    = blockIdx.y;    // 0..31
    const int tid   = threadIdx.x;   // 0..63

    const float4* Kp4 = reinterpret_cast<const float4*>(g_K + (size_t)bh * Tseq * HD);
    const float4* Vp4 = reinterpret_cast<const float4*>(g_V + (size_t)bh * Tseq * HD);

    const int qi = qtile * 64 + tid;

    float q[HD];
    {
        const float4* q4 = reinterpret_cast<const float4*>(
            g_Q + ((size_t)bh * Tseq + qi) * HD);
        #pragma unroll
        for (int d4 = 0; d4 < 16; ++d4) {
            float4 v = q4[d4];
            q[4*d4+0] = v.x * 0.125f;  // 1/sqrt(64)
            q[4*d4+1] = v.y * 0.125f;
            q[4*d4+2] = v.z * 0.125f;
            q[4*d4+3] = v.w * 0.125f;
        }
    }

    float acc[HD];
    #pragma unroll
    for (int d = 0; d < HD; ++d) acc[d] = 0.f;
    float m = -1e30f, l = 0.f;

    __shared__ float ks[64][HD];
    __shared__ float vs[64][HD];
    __shared__ float sbuf[64][64];

    for (int t0 = 0; t0 <= qtile; ++t0) {
        __syncthreads();
        {   // vectorized cooperative tile load: 1024 float4 per array
            const float4* Ksrc = Kp4 + (size_t)t0 * 64 * 16;
            const float4* Vsrc = Vp4 + (size_t)t0 * 64 * 16;
            float4* kd = reinterpret_cast<float4*>(&ks[0][0]);
            float4* vd = reinterpret_cast<float4*>(&vs[0][0]);
            #pragma unroll
            for (int i = 0; i < 16; ++i) {
                kd[i * 64 + tid] = Ksrc[i * 64 + tid];
                vd[i * 64 + tid] = Vsrc[i * 64 + tid];
            }
        }
        __syncthreads();

        const bool diag = (t0 == qtile);

        // ---- QK: scores into sbuf, track tile max ----
        float tmax = -1e30f;
        for (int j = 0; j < 64; ++j) {
            const float4* kr = reinterpret_cast<const float4*>(ks[j]);
            float s0 = 0.f, s1 = 0.f, s2 = 0.f, s3 = 0.f;
            #pragma unroll
            for (int d4 = 0; d4 < 16; ++d4) {
                float4 kv = kr[d4];                 // warp-broadcast LDS.128
                s0 = fmaf(q[4*d4+0], kv.x, s0);
                s1 = fmaf(q[4*d4+1], kv.y, s1);
                s2 = fmaf(q[4*d4+2], kv.z, s2);
                s3 = fmaf(q[4*d4+3], kv.w, s3);
            }
            float s = (s0 + s1) + (s2 + s3);
            if (diag && j > tid) s = -1e30f;        // causal mask, uniform flow
            sbuf[j][tid] = s;
            tmax = fmaxf(tmax, s);
        }

        float mnew = fmaxf(m, tmax);
        float corr = __expf(m - mnew);
        l *= corr;
        #pragma unroll
        for (int d = 0; d < HD; ++d) acc[d] *= corr;

        // ---- PV: weights + accumulate ----
        for (int j = 0; j < 64; ++j) {
            float p = __expf(sbuf[j][tid] - mnew);
            l += p;
            const float4* vr = reinterpret_cast<const float4*>(vs[j]);
            #pragma unroll
            for (int d4 = 0; d4 < 16; ++d4) {
                float4 vv = vr[d4];
                acc[4*d4+0] = fmaf(p, vv.x, acc[4*d4+0]);
                acc[4*d4+1] = fmaf(p, vv.y, acc[4*d4+1]);
                acc[4*d4+2] = fmaf(p, vv.z, acc[4*d4+2]);
                acc[4*d4+3] = fmaf(p, vv.w, acc[4*d4+3]);
            }
        }
        m = mnew;
    }

    const float inv = 1.f / l;
    const int b = bh >> 4;
    const int h = bh & 15;
    float4* op = reinterpret_cast<float4*>(
        g_att + (size_t)(b * Tseq + qi) * Cdim + h * HD);
    #pragma unroll
    for (int d4 = 0; d4 < 16; ++d4)
        op[d4] = make_float4(acc[4*d4+0]*inv, acc[4*d4+1]*inv,
                             acc[4*d4+2]*inv, acc[4*d4+3]*inv);
}

// ======================================================================
extern "C" void kernel_launch(void* const* d_in, const int* in_sizes, int n_in,
                              void* d_out, int out_size)
{
    const float* x      = (const float*)d_in[0];
    const float* w_attn = (const float*)d_in[1];
    const float* w_proj = (const float*)d_in[2];
    float* out = (float*)d_out;

    // 0) rope tables (tiny)
    rope_table_kernel<<<(Tseq * 32) / 256, 256>>>();

    // 1) QKV = x @ w_attn^T -> g_qkv
    gemm_nt<0><<<dim3(QKVN / 128, MROWS / 128), 256>>>(x, w_attn, nullptr,
                                                       MROWS, QKVN, Cdim);

    // 2) RoPE + split to [B,H,T,hd]
    rope_kernel<<<(Bsz * Tseq * Hn * 32) / 256, 256>>>();

    // 3) causal flash attention -> g_att [B,T,C]
    attn_kernel<<<dim3(Tseq / 64, BHn), 64>>>();

    // 4) out = g_att @ w_proj^T
    gemm_nt<1><<<dim3(Cdim / 128, MROWS / 128), 256>>>(nullptr, w_proj, out,
                                                       MROWS, Cdim, Cdim);
}